// round 15
// baseline (speedup 1.0000x reference)
#include <cuda_runtime.h>
#include <math.h>
#include <float.h>

#define BS 32
#define NQ 300
#define NC 2001
#define NT 25
#define NQP 308   // padded row: 77 16B-granules, 77 coprime 8 => conflict-free
#define CPB 38    // cost blocks per batch (38 * 8 warps = 304 >= 300)

__device__ float g_cost[BS * NT * NQ];
__device__ unsigned g_done[BS];

__global__ void init_kernel() {
    if (threadIdx.x < BS) g_done[threadIdx.x] = 0u;
}

// ---------------------------------------------------------------------------
// Producer kernel (PDL primary): softmax cost, batch-aligned blocks.
// Low register count => full occupancy, split-kernel bandwidth.
// ---------------------------------------------------------------------------
__global__ __launch_bounds__(256)
void cost_kernel(const float* __restrict__ logits,
                 const int* __restrict__ targets) {
    const unsigned FULL = 0xffffffffu;
#if __CUDA_ARCH__ >= 900
    cudaTriggerProgrammaticLaunchCompletion();
#endif
    int tid  = threadIdx.x;
    int wid  = tid >> 5;
    int lane = tid & 31;
    int cb   = blockIdx.x;
    int b    = cb / CPB;
    int part = cb % CPB;
    int q    = part * 8 + wid;                // 8 warps per block
    if (q < NQ) {
        const float* row = logits + ((size_t)b * NQ + q) * NC;

        float m = -FLT_MAX;
        for (int c = lane; c < NC; c += 32) m = fmaxf(m, row[c]);
        #pragma unroll
        for (int o = 16; o; o >>= 1) m = fmaxf(m, __shfl_xor_sync(FULL, m, o));

        float s = 0.f;
        for (int c = lane; c < NC; c += 32) s += expf(row[c] - m);
        #pragma unroll
        for (int o = 16; o; o >>= 1) s += __shfl_xor_sync(FULL, s, o);

        if (lane < NT) {
            int cls = targets[b * NT + lane];
            float p = expf(row[cls] - m) / s;
            g_cost[((size_t)b * NT + lane) * NQ + q] = -p;
        }
    }
    __syncthreads();
    __threadfence();                           // release g_cost stores
    if (tid == 0) atomicAdd(&g_done[b], 1u);
}

// monotonic float<->uint order-preserving transform (conflict path only)
__device__ __forceinline__ unsigned fkey(float x) {
    unsigned v = __float_as_uint(x);
    return (v & 0x80000000u) ? ~v : (v | 0x80000000u);
}
__device__ __forceinline__ float funkey(unsigned k) {
    unsigned v = (k & 0x80000000u) ? (k ^ 0x80000000u) : ~k;
    return __uint_as_float(v);
}

// Lane-local argmin_j (C[r][j] - v[j]), j ascending, exact first-min ties.
__device__ __forceinline__ float lane_scan(const float* __restrict__ C,
                                           const float* __restrict__ v_sm,
                                           int r, int* bj_out) {
    const float4* Crow = (const float4*)(C + r * NQP);
    const float4* V    = (const float4*)v_sm;
    float b0 = FLT_MAX, b1 = FLT_MAX, b2 = FLT_MAX, b3 = FLT_MAX;
    int   j0 = 0, j1 = 1, j2 = 2, j3 = 3;
    #pragma unroll 5
    for (int k = 0; k < 75; k++) {
        float4 c = Crow[k];
        float4 v = V[k];
        float d0 = c.x - v.x, d1 = c.y - v.y, d2 = c.z - v.z, d3 = c.w - v.w;
        if (d0 < b0) { b0 = d0; j0 = 4*k;     }
        if (d1 < b1) { b1 = d1; j1 = 4*k + 1; }
        if (d2 < b2) { b2 = d2; j2 = 4*k + 2; }
        if (d3 < b3) { b3 = d3; j3 = 4*k + 3; }
    }
    if (b1 < b0 || (b1 == b0 && j1 < j0)) { b0 = b1; j0 = j1; }
    if (b3 < b2 || (b3 == b2 && j3 < j2)) { b2 = b3; j2 = j3; }
    if (b2 < b0 || (b2 == b0 && j2 < j0)) { b0 = b2; j0 = j2; }
    *bj_out = j0;
    return b0;
}

// ---------------------------------------------------------------------------
// Consumer kernel (PDL secondary): one block (one warp) per batch. Polls its
// batch's producer-done flag, then runs the R11-verified JV LSAP.
// ---------------------------------------------------------------------------
__global__ void lsap_kernel(float* __restrict__ out) {
    const unsigned FULL = 0xffffffffu;
    int b    = blockIdx.x;
    int lane = threadIdx.x;   // blockDim.x == 32

    if (lane == 0) {
        while (atomicAdd(&g_done[b], 0u) < (unsigned)CPB) __nanosleep(200);
    }
    __syncwarp();
    __threadfence();                           // acquire g_cost stores

    __shared__ alignas(16) float C[NT * NQP];
    __shared__ alignas(16) float v_sm[NQP];
    __shared__ alignas(16) int   path[NQ];
    __shared__ float u[NT];
    __shared__ int   col4row_sm[NT];
    __shared__ int   sr[NT];
    __shared__ float disc[NT];

    {   // load g_cost (unpadded) into padded smem rows, no div/mod
        const float4* src = (const float4*)(g_cost + (size_t)b * NT * NQ);
        float4* dst = (float4*)C;
        int row = 0, g = lane;
        for (int k = lane; k < NT * 75; k += 32) {
            dst[row * 77 + g] = src[k];
            g += 32; if (g >= 75) { g -= 75; row++; }
        }
    }
    {
        float4 z = make_float4(0.f, 0.f, 0.f, 0.f);
        float4* vz = (float4*)v_sm;
        for (int k = lane; k < NQP / 4; k += 32) vz[k] = z;
    }
    if (lane < NT) { u[lane] = 0.f; col4row_sm[lane] = -1; }
    __syncwarp();

    const bool arow = (lane < NT);   // lane owns row `lane`
    float vv[12];
    #pragma unroll
    for (int s = 0; s < 12; s++) vv[s] = 0.f;

    // all 25 first-pop argmins in one parallel reduction-free scan
    float cbv = FLT_MAX; int cbj = 0;
    if (arow) cbv = lane_scan(C, v_sm, lane, &cbj);

    int my_col = -1;   // col4row for row `lane`, register-resident

    for (int cur = 0; cur < NT; cur++) {
        float minVal = __shfl_sync(FULL, cbv, cur);
        int   bestj  = __shfl_sync(FULL, cbj, cur);

        unsigned asg = __ballot_sync(FULL, my_col == bestj);
        if (asg == 0u) {
            // fast path: single-pop search (v unchanged, u[cur] = minVal)
            if (lane == cur) my_col = bestj;
            if (lane == 0) {
                u[cur] = minVal;
                col4row_sm[cur] = bestj;
            }
            continue;
        }

        // ---- conflict: exact general JV search ----
        int i = __ffs(asg) - 1;              // row currently holding bestj
        __syncwarp();                        // fence prior lane-0 stores

        // distributed seed d[j] = C[cur][j] - v[j], cols 12*lane..12*lane+12
        float sh[12];
        if (arow) {
            const float4* Crow = (const float4*)&C[cur * NQP + 12 * lane];
            float4 c0 = Crow[0], c1 = Crow[1], c2 = Crow[2];
            sh[0]=c0.x-vv[0];  sh[1]=c0.y-vv[1];  sh[2]=c0.z-vv[2];  sh[3]=c0.w-vv[3];
            sh[4]=c1.x-vv[4];  sh[5]=c1.y-vv[5];  sh[6]=c1.z-vv[6];  sh[7]=c1.w-vv[7];
            sh[8]=c2.x-vv[8];  sh[9]=c2.y-vv[9];  sh[10]=c2.z-vv[10]; sh[11]=c2.w-vv[11];
        } else {
            #pragma unroll
            for (int s = 0; s < 12; s++) sh[s] = FLT_MAX;
        }
        unsigned scm = arow ? 0u : 0xFFFu;   // scanned-column mask per lane
        if (arow) {                          // path[j] = cur for all j
            int4 pc = make_int4(cur, cur, cur, cur);
            int4* pp = (int4*)&path[12 * lane];
            pp[0] = pc; pp[1] = pc; pp[2] = pc;
        }
        if (lane == bestj / 12) scm |= 1u << (bestj % 12);
        if (lane == 0) { sr[0] = cur; disc[0] = 0.f; }
        int nsr  = 1;
        int sink = -1;

        while (true) {
            if (lane == 0) { sr[nsr] = i; disc[nsr] = minVal; }
            nsr++;
            float ui = u[i];                  // LDS, overlaps C-row load
            float am = minVal - ui;           // exact 0 for duplicate rows
            float ca0 = FLT_MAX, ca1 = FLT_MAX, ca2 = FLT_MAX, ca3 = FLT_MAX;
            int   cs0 = 12, cs1 = 12, cs2 = 12, cs3 = 12;
            if (arow) {
                const float4* Crow = (const float4*)&C[i * NQP + 12 * lane];
                float4 c0 = Crow[0], c1 = Crow[1], c2 = Crow[2];
                float cc[12] = {c0.x,c0.y,c0.z,c0.w, c1.x,c1.y,c1.z,c1.w,
                                c2.x,c2.y,c2.z,c2.w};
                float ca[4] = {FLT_MAX, FLT_MAX, FLT_MAX, FLT_MAX};
                int   cs[4] = {12, 12, 12, 12};
                #pragma unroll
                for (int s = 0; s < 12; s++) {
                    if (!((scm >> s) & 1u)) {
                        float dd = (cc[s] + am) - vv[s];
                        if (dd < sh[s]) { sh[s] = dd; path[12*lane + s] = i; }
                        int m = s & 3;
                        if (sh[s] < ca[m]) { ca[m] = sh[s]; cs[m] = s; }
                    }
                }
                ca0 = ca[0]; ca1 = ca[1]; ca2 = ca[2]; ca3 = ca[3];
                cs0 = cs[0]; cs1 = cs[1]; cs2 = cs[2]; cs3 = cs[3];
            }
            // lexicographic merge of the 4 chains (exact first-min)
            if (ca1 < ca0 || (ca1 == ca0 && cs1 < cs0)) { ca0 = ca1; cs0 = cs1; }
            if (ca3 < ca2 || (ca3 == ca2 && cs3 < cs2)) { ca2 = ca3; cs2 = cs3; }
            if (ca2 < ca0 || (ca2 == ca0 && cs2 < cs0)) { ca0 = ca2; cs0 = cs2; }

            unsigned k2 = (cs0 < 12) ? fkey(ca0) : 0xFFFFFFFFu;
            unsigned mk = __reduce_min_sync(FULL, k2);
            unsigned mj = (k2 == mk && cs0 < 12) ? (unsigned)(12*lane + cs0)
                                                 : 0xFFFFFFFFu;
            int bj = (int)__reduce_min_sync(FULL, mj);
            minVal = funkey(mk);
            if (lane == bj / 12) scm |= 1u << (bj % 12);
            // who holds column bj? (assignments frozen during the search)
            unsigned hb = __ballot_sync(FULL, my_col == bj);
            if (hb == 0u) { sink = bj; break; }
            i = __ffs(hb) - 1;
        }

        // v duals on scanned columns (registers + smem mirror for lane scans)
        if (arow) {
            #pragma unroll
            for (int s = 0; s < 12; s++) {
                if ((scm >> s) & 1u) {
                    vv[s] -= minVal - sh[s];
                    v_sm[12 * lane + s] = vv[s];
                }
            }
        }
        __syncwarp();
        if (lane == 0) {
            u[cur] += minVal;
            for (int k = 1; k < nsr; k++) u[sr[k]] += minVal - disc[k];
            int j = sink;
            while (true) {
                int i2 = path[j];
                int nxt = col4row_sm[i2];
                col4row_sm[i2] = j;
                j = nxt;
                if (i2 == cur) break;
            }
        }
        __syncwarp();
        // refresh register assignment state (augment may reshuffle columns)
        if (arow) my_col = col4row_sm[lane];
        // eager parallel rescan of stale caches (R9/R10-validated invariant)
        unsigned oscm = __shfl_sync(FULL, scm, cbj / 12);
        bool stale = arow && (lane > cur) && ((oscm >> (cbj % 12)) & 1u);
        if (stale) cbv = lane_scan(C, v_sm, lane, &cbj);
    }

    // stable argsort of distinct ints by rank counting; graded as float32.
    __syncwarp();
    if (lane < NT) {
        int myv = col4row_sm[lane];
        int pos = 0;
        #pragma unroll
        for (int t = 0; t < NT; t++) pos += (col4row_sm[t] < myv) ? 1 : 0;
        out[b * NT + pos]           = (float)myv;   // row_inds
        out[BS * NT + b * NT + pos] = (float)lane;  // col_inds
    }
}

// ---------------------------------------------------------------------------
extern "C" void kernel_launch(void* const* d_in, const int* in_sizes, int n_in,
                              void* d_out, int out_size) {
    const float* logits  = (const float*)d_in[0];   // [32, 300, 2001] f32
    const int*   targets = (const int*)d_in[1];     // [32, 25] i32
    float*       out     = (float*)d_out;           // [2, 32, 25] graded as f32

    init_kernel<<<1, 32>>>();
    cost_kernel<<<BS * CPB, 256>>>(logits, targets);

    // Secondary with programmatic stream serialization relaxed (PDL): may
    // enter the SMs while cost_kernel drains; per-batch g_done flags carry
    // the real data dependency. If PDL is unavailable, falls back to serial.
    cudaLaunchConfig_t cfg = {};
    cfg.gridDim  = dim3(BS, 1, 1);
    cfg.blockDim = dim3(32, 1, 1);
    cudaLaunchAttribute attrs[1];
    attrs[0].id = cudaLaunchAttributeProgrammaticStreamSerialization;
    attrs[0].val.programmaticStreamSerializationAllowed = 1;
    cfg.attrs = attrs;
    cfg.numAttrs = 1;
    cudaLaunchKernelEx(&cfg, lsap_kernel, out);
}

// round 17
// speedup vs baseline: 1.7599x; 1.7599x over previous
#include <cuda_runtime.h>
#include <math.h>
#include <float.h>

#define BS 32
#define NQ 300
#define NC 2001
#define NT 25
#define NQP 308   // padded row: 77 16B-granules, 77 coprime 8 => conflict-free

// Scratch cost matrix, stored transposed as [b][t][q].
__device__ float g_cost[BS * NT * NQ];

// ---------------------------------------------------------------------------
// Phase A: softmax over classes + gather target-class probs (R11 verbatim).
// ---------------------------------------------------------------------------
__global__ void cost_kernel(const float* __restrict__ logits,
                            const int* __restrict__ targets) {
    const unsigned FULL = 0xffffffffu;
    int gwarp = (blockIdx.x * blockDim.x + threadIdx.x) >> 5;
    int lane  = threadIdx.x & 31;
    if (gwarp >= BS * NQ) return;
    int b = gwarp / NQ;
    int q = gwarp % NQ;

    const float* row = logits + ((size_t)b * NQ + q) * NC;

    float m = -FLT_MAX;
    for (int c = lane; c < NC; c += 32) m = fmaxf(m, row[c]);
    #pragma unroll
    for (int o = 16; o; o >>= 1) m = fmaxf(m, __shfl_xor_sync(FULL, m, o));

    float s = 0.f;
    for (int c = lane; c < NC; c += 32) s += expf(row[c] - m);
    #pragma unroll
    for (int o = 16; o; o >>= 1) s += __shfl_xor_sync(FULL, s, o);

    if (lane < NT) {
        int cls = targets[b * NT + lane];
        float p = expf(row[cls] - m) / s;
        g_cost[((size_t)b * NT + lane) * NQ + q] = -p;
    }
}

// monotonic float<->uint order-preserving transform (conflict path only)
__device__ __forceinline__ unsigned fkey(float x) {
    unsigned v = __float_as_uint(x);
    return (v & 0x80000000u) ? ~v : (v | 0x80000000u);
}
__device__ __forceinline__ float funkey(unsigned k) {
    unsigned v = (k & 0x80000000u) ? (k ^ 0x80000000u) : ~k;
    return __uint_as_float(v);
}

// Lane-local argmin_j (C[r][j] - v[j]), j ascending, exact first-min ties.
__device__ __forceinline__ float lane_scan(const float* __restrict__ C,
                                           const float* __restrict__ v_sm,
                                           int r, int* bj_out) {
    const float4* Crow = (const float4*)(C + r * NQP);
    const float4* V    = (const float4*)v_sm;
    float b0 = FLT_MAX, b1 = FLT_MAX, b2 = FLT_MAX, b3 = FLT_MAX;
    int   j0 = 0, j1 = 1, j2 = 2, j3 = 3;
    #pragma unroll 5
    for (int k = 0; k < 75; k++) {
        float4 c = Crow[k];
        float4 v = V[k];
        float d0 = c.x - v.x, d1 = c.y - v.y, d2 = c.z - v.z, d3 = c.w - v.w;
        if (d0 < b0) { b0 = d0; j0 = 4*k;     }
        if (d1 < b1) { b1 = d1; j1 = 4*k + 1; }
        if (d2 < b2) { b2 = d2; j2 = 4*k + 2; }
        if (d3 < b3) { b3 = d3; j3 = 4*k + 3; }
    }
    if (b1 < b0 || (b1 == b0 && j1 < j0)) { b0 = b1; j0 = j1; }
    if (b3 < b2 || (b3 == b2 && j3 < j2)) { b2 = b3; j2 = j3; }
    if (b2 < b0 || (b2 == b0 && j2 < j0)) { b0 = b2; j0 = j2; }
    *bj_out = j0;
    return b0;
}

// ---------------------------------------------------------------------------
// Phase B: JV LSAP, one warp per batch (R11 structure). Change vs R11: the
// alternating-tree bookkeeping (sr, disc) lives in per-lane registers (lane k
// records pop k), and the post-search u-dual update runs in PARALLEL across
// lanes instead of lane-0 serially (identical arithmetic, distinct addresses).
// ---------------------------------------------------------------------------
__global__ void lsap_kernel(float* __restrict__ out) {
    const unsigned FULL = 0xffffffffu;
    int b    = blockIdx.x;
    int lane = threadIdx.x;   // blockDim.x == 32

    __shared__ alignas(16) float C[NT * NQP];
    __shared__ alignas(16) float v_sm[NQP];
    __shared__ alignas(16) int   path[NQ];
    __shared__ float u[NT];
    __shared__ int   col4row_sm[NT];

    {   // load g_cost (unpadded) into padded smem rows, no div/mod
        const float4* src = (const float4*)(g_cost + (size_t)b * NT * NQ);
        float4* dst = (float4*)C;
        int row = 0, g = lane;
        for (int k = lane; k < NT * 75; k += 32) {
            dst[row * 77 + g] = src[k];
            g += 32; if (g >= 75) { g -= 75; row++; }
        }
    }
    {
        float4 z = make_float4(0.f, 0.f, 0.f, 0.f);
        float4* vz = (float4*)v_sm;
        for (int k = lane; k < NQP / 4; k += 32) vz[k] = z;
    }
    if (lane < NT) { u[lane] = 0.f; col4row_sm[lane] = -1; }
    __syncwarp();

    const bool arow = (lane < NT);   // lane owns row `lane`
    float vv[12];
    #pragma unroll
    for (int s = 0; s < 12; s++) vv[s] = 0.f;

    // all 25 first-pop argmins in one parallel reduction-free scan
    float cbv = FLT_MAX; int cbj = 0;
    if (arow) cbv = lane_scan(C, v_sm, lane, &cbj);

    int my_col = -1;   // col4row for row `lane`, register-resident

    for (int cur = 0; cur < NT; cur++) {
        float minVal = __shfl_sync(FULL, cbv, cur);
        int   bestj  = __shfl_sync(FULL, cbj, cur);

        unsigned asg = __ballot_sync(FULL, my_col == bestj);
        if (asg == 0u) {
            // fast path: single-pop search (v unchanged, u[cur] = minVal)
            if (lane == cur) my_col = bestj;
            if (lane == 0) {
                u[cur] = minVal;
                col4row_sm[cur] = bestj;
            }
            continue;
        }

        // ---- conflict: exact general JV search ----
        int i = __ffs(asg) - 1;              // row currently holding bestj
        __syncwarp();                        // fence prior lane-0 stores

        // distributed seed d[j] = C[cur][j] - v[j], cols 12*lane..12*lane+12
        float sh[12];
        if (arow) {
            const float4* Crow = (const float4*)&C[cur * NQP + 12 * lane];
            float4 c0 = Crow[0], c1 = Crow[1], c2 = Crow[2];
            sh[0]=c0.x-vv[0];  sh[1]=c0.y-vv[1];  sh[2]=c0.z-vv[2];  sh[3]=c0.w-vv[3];
            sh[4]=c1.x-vv[4];  sh[5]=c1.y-vv[5];  sh[6]=c1.z-vv[6];  sh[7]=c1.w-vv[7];
            sh[8]=c2.x-vv[8];  sh[9]=c2.y-vv[9];  sh[10]=c2.z-vv[10]; sh[11]=c2.w-vv[11];
        } else {
            #pragma unroll
            for (int s = 0; s < 12; s++) sh[s] = FLT_MAX;
        }
        unsigned scm = arow ? 0u : 0xFFFu;   // scanned-column mask per lane
        if (arow) {                          // path[j] = cur for all j
            int4 pc = make_int4(cur, cur, cur, cur);
            int4* pp = (int4*)&path[12 * lane];
            pp[0] = pc; pp[1] = pc; pp[2] = pc;
        }
        if (lane == bestj / 12) scm |= 1u << (bestj % 12);

        // alternating-tree record, per-lane registers: lane k holds pop k
        int   reg_sr   = cur;                // lane 0's entry (cur, 0)
        float reg_disc = 0.f;
        int nsr  = 1;
        int sink = -1;

        while (true) {
            if (lane == nsr) { reg_sr = i; reg_disc = minVal; }
            nsr++;
            float ui = u[i];                  // LDS, overlaps C-row load
            float am = minVal - ui;           // exact 0 for duplicate rows
            float ca0 = FLT_MAX, ca1 = FLT_MAX, ca2 = FLT_MAX, ca3 = FLT_MAX;
            int   cs0 = 12, cs1 = 12, cs2 = 12, cs3 = 12;
            if (arow) {
                const float4* Crow = (const float4*)&C[i * NQP + 12 * lane];
                float4 c0 = Crow[0], c1 = Crow[1], c2 = Crow[2];
                float cc[12] = {c0.x,c0.y,c0.z,c0.w, c1.x,c1.y,c1.z,c1.w,
                                c2.x,c2.y,c2.z,c2.w};
                float ca[4] = {FLT_MAX, FLT_MAX, FLT_MAX, FLT_MAX};
                int   cs[4] = {12, 12, 12, 12};
                #pragma unroll
                for (int s = 0; s < 12; s++) {
                    if (!((scm >> s) & 1u)) {
                        float dd = (cc[s] + am) - vv[s];
                        if (dd < sh[s]) { sh[s] = dd; path[12*lane + s] = i; }
                        int m = s & 3;
                        if (sh[s] < ca[m]) { ca[m] = sh[s]; cs[m] = s; }
                    }
                }
                ca0 = ca[0]; ca1 = ca[1]; ca2 = ca[2]; ca3 = ca[3];
                cs0 = cs[0]; cs1 = cs[1]; cs2 = cs[2]; cs3 = cs[3];
            }
            // lexicographic merge of the 4 chains (exact first-min)
            if (ca1 < ca0 || (ca1 == ca0 && cs1 < cs0)) { ca0 = ca1; cs0 = cs1; }
            if (ca3 < ca2 || (ca3 == ca2 && cs3 < cs2)) { ca2 = ca3; cs2 = cs3; }
            if (ca2 < ca0 || (ca2 == ca0 && cs2 < cs0)) { ca0 = ca2; cs0 = cs2; }

            unsigned k2 = (cs0 < 12) ? fkey(ca0) : 0xFFFFFFFFu;
            unsigned mk = __reduce_min_sync(FULL, k2);
            unsigned mj = (k2 == mk && cs0 < 12) ? (unsigned)(12*lane + cs0)
                                                 : 0xFFFFFFFFu;
            int bj = (int)__reduce_min_sync(FULL, mj);
            minVal = funkey(mk);
            if (lane == bj / 12) scm |= 1u << (bj % 12);
            // who holds column bj? (assignments frozen during the search)
            unsigned hb = __ballot_sync(FULL, my_col == bj);
            if (hb == 0u) { sink = bj; break; }
            i = __ffs(hb) - 1;
        }

        // v duals on scanned columns (registers + smem mirror for lane scans)
        if (arow) {
            #pragma unroll
            for (int s = 0; s < 12; s++) {
                if ((scm >> s) & 1u) {
                    vv[s] -= minVal - sh[s];
                    v_sm[12 * lane + s] = vv[s];
                }
            }
        }
        // u duals in PARALLEL: lane k updates u[sr_k] += minVal - disc_k.
        // Lane 0: u[cur] += minVal (disc_0 = 0). Distinct addresses.
        if (lane < nsr) u[reg_sr] += minVal - reg_disc;
        __syncwarp();
        if (lane == 0) {
            int j = sink;
            while (true) {
                int i2 = path[j];
                int nxt = col4row_sm[i2];
                col4row_sm[i2] = j;
                j = nxt;
                if (i2 == cur) break;
            }
        }
        __syncwarp();
        // refresh register assignment state (augment may reshuffle columns)
        if (arow) my_col = col4row_sm[lane];
        // eager parallel rescan of stale caches (R9/R10-validated invariant)
        unsigned oscm = __shfl_sync(FULL, scm, cbj / 12);
        bool stale = arow && (lane > cur) && ((oscm >> (cbj % 12)) & 1u);
        if (stale) cbv = lane_scan(C, v_sm, lane, &cbj);
    }

    // stable argsort of distinct ints by rank counting; graded as float32.
    __syncwarp();
    if (lane < NT) {
        int myv = col4row_sm[lane];
        int pos = 0;
        #pragma unroll
        for (int t = 0; t < NT; t++) pos += (col4row_sm[t] < myv) ? 1 : 0;
        out[b * NT + pos]           = (float)myv;   // row_inds
        out[BS * NT + b * NT + pos] = (float)lane;  // col_inds
    }
}

// ---------------------------------------------------------------------------
extern "C" void kernel_launch(void* const* d_in, const int* in_sizes, int n_in,
                              void* d_out, int out_size) {
    const float* logits  = (const float*)d_in[0];   // [32, 300, 2001] f32
    const int*   targets = (const int*)d_in[1];     // [32, 25] i32
    float*       out     = (float*)d_out;           // [2, 32, 25] graded as f32

    int total_warps = BS * NQ;
    int threads = 256;
    int blocks = (total_warps * 32 + threads - 1) / threads;
    cost_kernel<<<blocks, threads>>>(logits, targets);

    lsap_kernel<<<BS, 32>>>(out);
}